// round 1
// baseline (speedup 1.0000x reference)
#include <cuda_runtime.h>
#include <math.h>

#define Bk   8
#define OBS0 80
#define OBS1 160
#define OBS2 384
#define TB   4        // batch rows per CTA
#define RK   32       // TB*Bk

// ---------------- per-launch precomputed scratch (static device memory) ----
__device__ float g_WkT[256 * 256];      // Wk transposed
__device__ float g_P[256 * 256];        // P = Wq @ Wk^T
__device__ float g_G[3 * 256 * 128];    // G_h = Wcv @ W_out[h*256:(h+1)*256, :]
__device__ float g_V2[256 * 128];       // V2 = Wv @ G2
__device__ float g_H[768 * 64];         // [H0;H1;H2], H_h = (·) @ W_j1
__device__ float g_c[64];               // c = b_out @ W_j1 + b_j1

// ---------------- precompute kernels ---------------------------------------
__global__ void pre0_transpose(const float* __restrict__ Wk) {
    int t = blockIdx.x, d = threadIdx.x;
    g_WkT[t * 256 + d] = Wk[d * 256 + t];
}

__global__ void pre1(const float* __restrict__ Wq, const float* __restrict__ Wcv,
                     const float* __restrict__ W_out) {
    __shared__ float row[256];
    int bid = blockIdx.x, tid = threadIdx.x;
    if (bid < 256) {
        // P row bid
        row[tid] = Wq[bid * 256 + tid];
        __syncthreads();
        float acc = 0.f;
#pragma unroll 8
        for (int t = 0; t < 256; t++)
            acc = fmaf(row[t], g_WkT[t * 256 + tid], acc);
        g_P[bid * 256 + tid] = acc;
    } else {
        int idx = bid - 256;           // 0..767
        int h = idx >> 8, dd = idx & 255;
        row[tid] = Wcv[dd * 256 + tid];
        __syncthreads();
        if (tid < 128) {
            float acc = 0.f;
#pragma unroll 8
            for (int e = 0; e < 256; e++)
                acc = fmaf(row[e], W_out[(h * 256 + e) * 128 + tid], acc);
            g_G[(h * 256 + dd) * 128 + tid] = acc;
        }
    }
}

__global__ void pre2(const float* __restrict__ Wv, const float* __restrict__ W_j1,
                     const float* __restrict__ b_out, const float* __restrict__ b_j1) {
    __shared__ float row[256];
    int bid = blockIdx.x, tid = threadIdx.x;   // 128 threads
    if (bid < 256) {
        // V2 row bid = Wv row @ G2
        row[tid]       = Wv[bid * 256 + tid];
        row[tid + 128] = Wv[bid * 256 + tid + 128];
        __syncthreads();
        float acc = 0.f;
#pragma unroll 8
        for (int e = 0; e < 256; e++)
            acc = fmaf(row[e], g_G[(512 + e) * 128 + tid], acc);
        g_V2[bid * 128 + tid] = acc;
    } else if (bid < 768) {
        int d = bid - 256;             // 0..511 -> rows of [G0;G1]
        row[tid] = g_G[d * 128 + tid];
        __syncthreads();
        if (tid < 64) {
            float acc = 0.f;
#pragma unroll 8
            for (int m = 0; m < 128; m++)
                acc = fmaf(row[m], W_j1[m * 64 + tid], acc);
            g_H[d * 64 + tid] = acc;
        }
    } else {
        if (tid < 64) {
            float acc = b_j1[tid];
#pragma unroll 8
            for (int m = 0; m < 128; m++)
                acc = fmaf(b_out[m], W_j1[m * 64 + tid], acc);
            g_c[tid] = acc;
        }
    }
}

__global__ void pre3(const float* __restrict__ W_j1) {
    __shared__ float row[128];
    int d2 = blockIdx.x, tid = threadIdx.x;    // 128 threads
    row[tid] = g_V2[d2 * 128 + tid];
    __syncthreads();
    if (tid < 64) {
        float acc = 0.f;
#pragma unroll 8
        for (int m = 0; m < 128; m++)
            acc = fmaf(row[m], W_j1[m * 64 + tid], acc);
        g_H[(512 + d2) * 64 + tid] = acc;
    }
}

// ---------------- main fused kernel -----------------------------------------
// smem: s2(12288) s0(320) s1(640) own(1024) env(1024) u(1024) S(8192)
//       sa(1024) sc(32) al(32) part(8)  = 25608 floats = 102432 B
#define SMEM_BYTES (25608 * 4)

extern __shared__ float sm[];

__global__ __launch_bounds__(256)
void critic_main(const float* __restrict__ state0,
                 const float* __restrict__ state1,
                 const float* __restrict__ state2,
                 const float* __restrict__ W_own, const float* __restrict__ b_own,
                 const float* __restrict__ W_env, const float* __restrict__ b_env,
                 const float* __restrict__ W_sur, const float* __restrict__ b_sur,
                 const float* __restrict__ W_j2,  const float* __restrict__ b_j2,
                 float* __restrict__ out) {
    float* s2  = sm;
    float* s0  = s2 + 12288;
    float* s1  = s0 + 320;
    float* own = s1 + 640;
    float* env = own + 1024;
    float* u   = env + 1024;
    float* S   = u + 1024;
    float* sa  = S + 8192;
    float* sc  = sa + 1024;
    float* al  = sc + 32;
    float* part = al + 32;

    const int tid = threadIdx.x;
    const int b0 = blockIdx.x * TB;

    // ---- cooperative loads ----
    {
        const float4* g = (const float4*)(state2 + (size_t)b0 * (Bk * OBS2));
        float4* dst = (float4*)s2;
#pragma unroll
        for (int i = 0; i < 12; i++) dst[tid + 256 * i] = g[tid + 256 * i];
        for (int i = tid; i < TB * OBS0; i += 256) s0[i] = state0[(size_t)b0 * OBS0 + i];
        for (int i = tid; i < TB * OBS1; i += 256) s1[i] = state1[(size_t)b0 * OBS1 + i];
    }
    __syncthreads();

    const int d = tid;   // output column 0..255

    // ---- own_e = relu(state0 @ W_own + b_own) ----
    {
        float a0 = 0.f, a1 = 0.f, a2 = 0.f, a3 = 0.f;
#pragma unroll 4
        for (int i = 0; i < OBS0; i++) {
            float w = W_own[i * 256 + d];
            a0 = fmaf(s0[0 * OBS0 + i], w, a0);
            a1 = fmaf(s0[1 * OBS0 + i], w, a1);
            a2 = fmaf(s0[2 * OBS0 + i], w, a2);
            a3 = fmaf(s0[3 * OBS0 + i], w, a3);
        }
        float bb = b_own[d];
        own[0 * 256 + d] = fmaxf(a0 + bb, 0.f);
        own[1 * 256 + d] = fmaxf(a1 + bb, 0.f);
        own[2 * 256 + d] = fmaxf(a2 + bb, 0.f);
        own[3 * 256 + d] = fmaxf(a3 + bb, 0.f);
    }
    // ---- env_e ----
    {
        float a0 = 0.f, a1 = 0.f, a2 = 0.f, a3 = 0.f;
#pragma unroll 4
        for (int i = 0; i < OBS1; i++) {
            float w = W_env[i * 256 + d];
            a0 = fmaf(s1[0 * OBS1 + i], w, a0);
            a1 = fmaf(s1[1 * OBS1 + i], w, a1);
            a2 = fmaf(s1[2 * OBS1 + i], w, a2);
            a3 = fmaf(s1[3 * OBS1 + i], w, a3);
        }
        float bb = b_env[d];
        env[0 * 256 + d] = fmaxf(a0 + bb, 0.f);
        env[1 * 256 + d] = fmaxf(a1 + bb, 0.f);
        env[2 * 256 + d] = fmaxf(a2 + bb, 0.f);
        env[3 * 256 + d] = fmaxf(a3 + bb, 0.f);
    }
    __syncthreads();

    // ---- u = own_e @ P  (score vector) ----
    {
        float a0 = 0.f, a1 = 0.f, a2 = 0.f, a3 = 0.f;
#pragma unroll 4
        for (int i = 0; i < 256; i++) {
            float p = g_P[i * 256 + d];
            a0 = fmaf(own[0 * 256 + i], p, a0);
            a1 = fmaf(own[1 * 256 + i], p, a1);
            a2 = fmaf(own[2 * 256 + i], p, a2);
            a3 = fmaf(own[3 * 256 + i], p, a3);
        }
        u[0 * 256 + d] = a0; u[1 * 256 + d] = a1;
        u[2 * 256 + d] = a2; u[3 * 256 + d] = a3;
    }

    // ---- S = relu(state2 @ W_sur + b_sur)  (dominant GEMM) ----
    {
        float acc[RK];
#pragma unroll
        for (int k = 0; k < RK; k++) acc[k] = 0.f;
#pragma unroll 2
        for (int i = 0; i < OBS2; i += 4) {
            float w0 = W_sur[(i + 0) * 256 + d];
            float w1 = W_sur[(i + 1) * 256 + d];
            float w2 = W_sur[(i + 2) * 256 + d];
            float w3 = W_sur[(i + 3) * 256 + d];
#pragma unroll
            for (int k = 0; k < RK; k++) {
                float4 s = *(const float4*)(s2 + k * OBS2 + i);
                acc[k] = fmaf(s.x, w0, fmaf(s.y, w1, fmaf(s.z, w2, fmaf(s.w, w3, acc[k]))));
            }
        }
        float bb = b_sur[d];
#pragma unroll
        for (int k = 0; k < RK; k++)
            S[k * 256 + d] = fmaxf(acc[k] + bb, 0.f);
    }
    __syncthreads();

    // ---- score + mask (warp w handles rk = w*4..w*4+3) ----
    {
        int warp = tid >> 5, lane = tid & 31;
#pragma unroll
        for (int t = 0; t < 4; t++) {
            int rk = warp * 4 + t;
            int r = rk >> 3;
            float dot = 0.f, ms = 0.f;
#pragma unroll
            for (int q = 0; q < 8; q++)
                dot = fmaf(S[rk * 256 + lane + 32 * q], u[r * 256 + lane + 32 * q], dot);
#pragma unroll
            for (int q = 0; q < 12; q++)
                ms += s2[rk * OBS2 + lane + 32 * q];
#pragma unroll
            for (int off = 16; off > 0; off >>= 1) {
                dot += __shfl_xor_sync(0xffffffffu, dot, off);
                ms  += __shfl_xor_sync(0xffffffffu, ms, off);
            }
            if (lane == 0)
                sc[rk] = (ms != 0.f) ? dot * 0.0625f : -INFINITY;
        }
    }
    __syncthreads();

    // ---- softmax over K=8 (warp 0; lane = r*8+k) ----
    if (tid < 32) {
        float s = sc[tid];
        float m = s;
#pragma unroll
        for (int off = 1; off < 8; off <<= 1)
            m = fmaxf(m, __shfl_xor_sync(0xffffffffu, m, off));
        float e = (s == -INFINITY) ? 0.f : expf(s - m);
        float sum = e;
#pragma unroll
        for (int off = 1; off < 8; off <<= 1)
            sum += __shfl_xor_sync(0xffffffffu, sum, off);
        al[tid] = e / sum;
    }
    __syncthreads();

    // ---- s_att = sum_k alpha_k * S_k ----
    {
#pragma unroll
        for (int r = 0; r < 4; r++) {
            float acc = 0.f;
#pragma unroll
            for (int k = 0; k < 8; k++)
                acc = fmaf(al[r * 8 + k], S[(r * 8 + k) * 256 + d], acc);
            sa[r * 256 + d] = acc;
        }
    }
    __syncthreads();

    // ---- hidden = relu([own,env,s_att] @ H + c); q = hidden @ W_j2 + b_j2 ----
    {
        int j = tid & 63, r = tid >> 6;
        float h = g_c[j];
#pragma unroll 4
        for (int dd = 0; dd < 256; dd++)
            h = fmaf(own[r * 256 + dd], g_H[dd * 64 + j], h);
#pragma unroll 4
        for (int dd = 0; dd < 256; dd++)
            h = fmaf(env[r * 256 + dd], g_H[(256 + dd) * 64 + j], h);
#pragma unroll 4
        for (int dd = 0; dd < 256; dd++)
            h = fmaf(sa[r * 256 + dd], g_H[(512 + dd) * 64 + j], h);
        h = fmaxf(h, 0.f);
        float v = h * W_j2[j];
#pragma unroll
        for (int off = 16; off > 0; off >>= 1)
            v += __shfl_xor_sync(0xffffffffu, v, off);
        if ((tid & 31) == 0) part[tid >> 5] = v;
    }
    __syncthreads();
    if (tid < TB)
        out[b0 + tid] = part[2 * tid] + part[2 * tid + 1] + b_j2[0];
}

// ---------------- launch ----------------------------------------------------
extern "C" void kernel_launch(void* const* d_in, const int* in_sizes, int n_in,
                              void* d_out, int out_size) {
    const float* state0 = (const float*)d_in[0];
    const float* state1 = (const float*)d_in[1];
    const float* state2 = (const float*)d_in[2];
    const float* W_own  = (const float*)d_in[3];
    const float* b_own  = (const float*)d_in[4];
    const float* W_env  = (const float*)d_in[5];
    const float* b_env  = (const float*)d_in[6];
    const float* W_sur  = (const float*)d_in[7];
    const float* b_sur  = (const float*)d_in[8];
    const float* Wq     = (const float*)d_in[9];
    const float* Wk     = (const float*)d_in[10];
    // d_in[11] = Wv; d_in[12] = Wcq (dead); d_in[13] = Wck (dead)
    const float* Wv     = (const float*)d_in[11];
    const float* Wcv    = (const float*)d_in[14];
    const float* W_out  = (const float*)d_in[15];
    const float* b_out  = (const float*)d_in[16];
    const float* W_j1   = (const float*)d_in[17];
    const float* b_j1   = (const float*)d_in[18];
    const float* W_j2   = (const float*)d_in[19];
    const float* b_j2   = (const float*)d_in[20];
    float* out = (float*)d_out;

    int B = in_sizes[0] / OBS0;   // 32768

    cudaFuncSetAttribute(critic_main, cudaFuncAttributeMaxDynamicSharedMemorySize,
                         SMEM_BYTES);

    pre0_transpose<<<256, 256>>>(Wk);
    pre1<<<1024, 256>>>(Wq, Wcv, W_out);
    pre2<<<769, 128>>>(Wv, W_j1, b_out, b_j1);
    pre3<<<256, 128>>>(W_j1);
    critic_main<<<B / TB, 256, SMEM_BYTES>>>(state0, state1, state2,
                                             W_own, b_own, W_env, b_env,
                                             W_sur, b_sur, W_j2, b_j2, out);
}

// round 2
// speedup vs baseline: 1.0024x; 1.0024x over previous
#include <cuda_runtime.h>
#include <math.h>

#define Bk   8
#define OBS0 80
#define OBS1 160
#define OBS2 384
#define TB   4        // batch rows per CTA
#define RK   32       // TB*Bk

// ---------------- per-launch precomputed scratch (static device memory) ----
__device__ float g_WkT[256 * 256];      // Wk transposed
__device__ float g_P[256 * 256];        // P = Wq @ Wk^T
__device__ float g_G[3 * 256 * 128];    // G_h = Wcv @ W_out[h*256:(h+1)*256, :]
__device__ float g_V2[256 * 128];       // V2 = Wv @ G2
__device__ float g_H[768 * 64];         // [H0;H1;H2], H_h = (·) @ W_j1
__device__ float g_c[64];               // c = b_out @ W_j1 + b_j1

// ---------------- precompute kernels ---------------------------------------
__global__ void pre0_transpose(const float* __restrict__ Wk) {
    int t = blockIdx.x, d = threadIdx.x;
    g_WkT[t * 256 + d] = Wk[d * 256 + t];
}

__global__ void pre1(const float* __restrict__ Wq, const float* __restrict__ Wcv,
                     const float* __restrict__ W_out) {
    __shared__ float row[256];
    int bid = blockIdx.x, tid = threadIdx.x;
    if (bid < 256) {
        // P row bid
        row[tid] = Wq[bid * 256 + tid];
        __syncthreads();
        float acc = 0.f;
#pragma unroll 8
        for (int t = 0; t < 256; t++)
            acc = fmaf(row[t], g_WkT[t * 256 + tid], acc);
        g_P[bid * 256 + tid] = acc;
    } else {
        int idx = bid - 256;           // 0..767
        int h = idx >> 8, dd = idx & 255;
        row[tid] = Wcv[dd * 256 + tid];
        __syncthreads();
        if (tid < 128) {
            float acc = 0.f;
#pragma unroll 8
            for (int e = 0; e < 256; e++)
                acc = fmaf(row[e], W_out[(h * 256 + e) * 128 + tid], acc);
            g_G[(h * 256 + dd) * 128 + tid] = acc;
        }
    }
}

__global__ void pre2(const float* __restrict__ Wv, const float* __restrict__ W_j1,
                     const float* __restrict__ b_out, const float* __restrict__ b_j1) {
    __shared__ float row[256];
    int bid = blockIdx.x, tid = threadIdx.x;   // 128 threads
    if (bid < 256) {
        // V2 row bid = Wv row @ G2
        row[tid]       = Wv[bid * 256 + tid];
        row[tid + 128] = Wv[bid * 256 + tid + 128];
        __syncthreads();
        float acc = 0.f;
#pragma unroll 8
        for (int e = 0; e < 256; e++)
            acc = fmaf(row[e], g_G[(512 + e) * 128 + tid], acc);
        g_V2[bid * 128 + tid] = acc;
    } else if (bid < 768) {
        int d = bid - 256;             // 0..511 -> rows of [G0;G1]
        row[tid] = g_G[d * 128 + tid];
        __syncthreads();
        if (tid < 64) {
            float acc = 0.f;
#pragma unroll 8
            for (int m = 0; m < 128; m++)
                acc = fmaf(row[m], W_j1[m * 64 + tid], acc);
            g_H[d * 64 + tid] = acc;
        }
    } else {
        if (tid < 64) {
            float acc = b_j1[tid];
#pragma unroll 8
            for (int m = 0; m < 128; m++)
                acc = fmaf(b_out[m], W_j1[m * 64 + tid], acc);
            g_c[tid] = acc;
        }
    }
}

__global__ void pre3(const float* __restrict__ W_j1) {
    __shared__ float row[128];
    int d2 = blockIdx.x, tid = threadIdx.x;    // 128 threads
    row[tid] = g_V2[d2 * 128 + tid];
    __syncthreads();
    if (tid < 64) {
        float acc = 0.f;
#pragma unroll 8
        for (int m = 0; m < 128; m++)
            acc = fmaf(row[m], W_j1[m * 64 + tid], acc);
        g_H[(512 + d2) * 64 + tid] = acc;
    }
}

// ---------------- main fused kernel -----------------------------------------
// smem: s2(12288) s0(320) s1(640) own(1024) env(1024) u(1024) S(8192)
//       sa(1024) sc(32) al(32) part(8)  = 25608 floats = 102432 B
#define SMEM_BYTES (25608 * 4)

extern __shared__ float sm[];

__global__ __launch_bounds__(256)
void critic_main(const float* __restrict__ state0,
                 const float* __restrict__ state1,
                 const float* __restrict__ state2,
                 const float* __restrict__ W_own, const float* __restrict__ b_own,
                 const float* __restrict__ W_env, const float* __restrict__ b_env,
                 const float* __restrict__ W_sur, const float* __restrict__ b_sur,
                 const float* __restrict__ W_j2,  const float* __restrict__ b_j2,
                 float* __restrict__ out) {
    float* s2  = sm;
    float* s0  = s2 + 12288;
    float* s1  = s0 + 320;
    float* own = s1 + 640;
    float* env = own + 1024;
    float* u   = env + 1024;
    float* S   = u + 1024;
    float* sa  = S + 8192;
    float* sc  = sa + 1024;
    float* al  = sc + 32;
    float* part = al + 32;

    const int tid = threadIdx.x;
    const int b0 = blockIdx.x * TB;

    // ---- cooperative loads ----
    {
        const float4* g = (const float4*)(state2 + (size_t)b0 * (Bk * OBS2));
        float4* dst = (float4*)s2;
#pragma unroll
        for (int i = 0; i < 12; i++) dst[tid + 256 * i] = g[tid + 256 * i];
        for (int i = tid; i < TB * OBS0; i += 256) s0[i] = state0[(size_t)b0 * OBS0 + i];
        for (int i = tid; i < TB * OBS1; i += 256) s1[i] = state1[(size_t)b0 * OBS1 + i];
    }
    __syncthreads();

    const int d = tid;   // output column 0..255

    // ---- own_e = relu(state0 @ W_own + b_own) ----
    {
        float a0 = 0.f, a1 = 0.f, a2 = 0.f, a3 = 0.f;
#pragma unroll 4
        for (int i = 0; i < OBS0; i++) {
            float w = W_own[i * 256 + d];
            a0 = fmaf(s0[0 * OBS0 + i], w, a0);
            a1 = fmaf(s0[1 * OBS0 + i], w, a1);
            a2 = fmaf(s0[2 * OBS0 + i], w, a2);
            a3 = fmaf(s0[3 * OBS0 + i], w, a3);
        }
        float bb = b_own[d];
        own[0 * 256 + d] = fmaxf(a0 + bb, 0.f);
        own[1 * 256 + d] = fmaxf(a1 + bb, 0.f);
        own[2 * 256 + d] = fmaxf(a2 + bb, 0.f);
        own[3 * 256 + d] = fmaxf(a3 + bb, 0.f);
    }
    // ---- env_e ----
    {
        float a0 = 0.f, a1 = 0.f, a2 = 0.f, a3 = 0.f;
#pragma unroll 4
        for (int i = 0; i < OBS1; i++) {
            float w = W_env[i * 256 + d];
            a0 = fmaf(s1[0 * OBS1 + i], w, a0);
            a1 = fmaf(s1[1 * OBS1 + i], w, a1);
            a2 = fmaf(s1[2 * OBS1 + i], w, a2);
            a3 = fmaf(s1[3 * OBS1 + i], w, a3);
        }
        float bb = b_env[d];
        env[0 * 256 + d] = fmaxf(a0 + bb, 0.f);
        env[1 * 256 + d] = fmaxf(a1 + bb, 0.f);
        env[2 * 256 + d] = fmaxf(a2 + bb, 0.f);
        env[3 * 256 + d] = fmaxf(a3 + bb, 0.f);
    }
    __syncthreads();

    // ---- u = own_e @ P  (score vector) ----
    {
        float a0 = 0.f, a1 = 0.f, a2 = 0.f, a3 = 0.f;
#pragma unroll 4
        for (int i = 0; i < 256; i++) {
            float p = g_P[i * 256 + d];
            a0 = fmaf(own[0 * 256 + i], p, a0);
            a1 = fmaf(own[1 * 256 + i], p, a1);
            a2 = fmaf(own[2 * 256 + i], p, a2);
            a3 = fmaf(own[3 * 256 + i], p, a3);
        }
        u[0 * 256 + d] = a0; u[1 * 256 + d] = a1;
        u[2 * 256 + d] = a2; u[3 * 256 + d] = a3;
    }

    // ---- S = relu(state2 @ W_sur + b_sur)  (dominant GEMM) ----
    {
        float acc[RK];
#pragma unroll
        for (int k = 0; k < RK; k++) acc[k] = 0.f;
#pragma unroll 2
        for (int i = 0; i < OBS2; i += 4) {
            float w0 = W_sur[(i + 0) * 256 + d];
            float w1 = W_sur[(i + 1) * 256 + d];
            float w2 = W_sur[(i + 2) * 256 + d];
            float w3 = W_sur[(i + 3) * 256 + d];
#pragma unroll
            for (int k = 0; k < RK; k++) {
                float4 s = *(const float4*)(s2 + k * OBS2 + i);
                acc[k] = fmaf(s.x, w0, fmaf(s.y, w1, fmaf(s.z, w2, fmaf(s.w, w3, acc[k]))));
            }
        }
        float bb = b_sur[d];
#pragma unroll
        for (int k = 0; k < RK; k++)
            S[k * 256 + d] = fmaxf(acc[k] + bb, 0.f);
    }
    __syncthreads();

    // ---- score + mask (warp w handles rk = w*4..w*4+3) ----
    {
        int warp = tid >> 5, lane = tid & 31;
#pragma unroll
        for (int t = 0; t < 4; t++) {
            int rk = warp * 4 + t;
            int r = rk >> 3;
            float dot = 0.f, ms = 0.f;
#pragma unroll
            for (int q = 0; q < 8; q++)
                dot = fmaf(S[rk * 256 + lane + 32 * q], u[r * 256 + lane + 32 * q], dot);
#pragma unroll
            for (int q = 0; q < 12; q++)
                ms += s2[rk * OBS2 + lane + 32 * q];
#pragma unroll
            for (int off = 16; off > 0; off >>= 1) {
                dot += __shfl_xor_sync(0xffffffffu, dot, off);
                ms  += __shfl_xor_sync(0xffffffffu, ms, off);
            }
            if (lane == 0)
                sc[rk] = (ms != 0.f) ? dot * 0.0625f : -INFINITY;
        }
    }
    __syncthreads();

    // ---- softmax over K=8 (warp 0; lane = r*8+k) ----
    if (tid < 32) {
        float s = sc[tid];
        float m = s;
#pragma unroll
        for (int off = 1; off < 8; off <<= 1)
            m = fmaxf(m, __shfl_xor_sync(0xffffffffu, m, off));
        float e = (s == -INFINITY) ? 0.f : expf(s - m);
        float sum = e;
#pragma unroll
        for (int off = 1; off < 8; off <<= 1)
            sum += __shfl_xor_sync(0xffffffffu, sum, off);
        al[tid] = e / sum;
    }
    __syncthreads();

    // ---- s_att = sum_k alpha_k * S_k ----
    {
#pragma unroll
        for (int r = 0; r < 4; r++) {
            float acc = 0.f;
#pragma unroll
            for (int k = 0; k < 8; k++)
                acc = fmaf(al[r * 8 + k], S[(r * 8 + k) * 256 + d], acc);
            sa[r * 256 + d] = acc;
        }
    }
    __syncthreads();

    // ---- hidden = relu([own,env,s_att] @ H + c); q = hidden @ W_j2 + b_j2 ----
    {
        int j = tid & 63, r = tid >> 6;
        float h = g_c[j];
#pragma unroll 4
        for (int dd = 0; dd < 256; dd++)
            h = fmaf(own[r * 256 + dd], g_H[dd * 64 + j], h);
#pragma unroll 4
        for (int dd = 0; dd < 256; dd++)
            h = fmaf(env[r * 256 + dd], g_H[(256 + dd) * 64 + j], h);
#pragma unroll 4
        for (int dd = 0; dd < 256; dd++)
            h = fmaf(sa[r * 256 + dd], g_H[(512 + dd) * 64 + j], h);
        h = fmaxf(h, 0.f);
        float v = h * W_j2[j];
#pragma unroll
        for (int off = 16; off > 0; off >>= 1)
            v += __shfl_xor_sync(0xffffffffu, v, off);
        if ((tid & 31) == 0) part[tid >> 5] = v;
    }
    __syncthreads();
    if (tid < TB)
        out[b0 + tid] = part[2 * tid] + part[2 * tid + 1] + b_j2[0];
}

// ---------------- launch ----------------------------------------------------
extern "C" void kernel_launch(void* const* d_in, const int* in_sizes, int n_in,
                              void* d_out, int out_size) {
    const float* state0 = (const float*)d_in[0];
    const float* state1 = (const float*)d_in[1];
    const float* state2 = (const float*)d_in[2];
    const float* W_own  = (const float*)d_in[3];
    const float* b_own  = (const float*)d_in[4];
    const float* W_env  = (const float*)d_in[5];
    const float* b_env  = (const float*)d_in[6];
    const float* W_sur  = (const float*)d_in[7];
    const float* b_sur  = (const float*)d_in[8];
    const float* Wq     = (const float*)d_in[9];
    const float* Wk     = (const float*)d_in[10];
    // d_in[11] = Wv; d_in[12] = Wcq (dead); d_in[13] = Wck (dead)
    const float* Wv     = (const float*)d_in[11];
    const float* Wcv    = (const float*)d_in[14];
    const float* W_out  = (const float*)d_in[15];
    const float* b_out  = (const float*)d_in[16];
    const float* W_j1   = (const float*)d_in[17];
    const float* b_j1   = (const float*)d_in[18];
    const float* W_j2   = (const float*)d_in[19];
    const float* b_j2   = (const float*)d_in[20];
    float* out = (float*)d_out;

    int B = in_sizes[0] / OBS0;   // 32768

    cudaFuncSetAttribute(critic_main, cudaFuncAttributeMaxDynamicSharedMemorySize,
                         SMEM_BYTES);

    pre0_transpose<<<256, 256>>>(Wk);
    pre1<<<1024, 256>>>(Wq, Wcv, W_out);
    pre2<<<769, 128>>>(Wv, W_j1, b_out, b_j1);
    pre3<<<256, 128>>>(W_j1);
    critic_main<<<B / TB, 256, SMEM_BYTES>>>(state0, state1, state2,
                                             W_own, b_own, W_env, b_env,
                                             W_sur, b_sur, W_j2, b_j2, out);
}

// round 3
// speedup vs baseline: 3.6824x; 3.6735x over previous
#include <cuda_runtime.h>
#include <math.h>
#include <stdint.h>

#define OBS0 80
#define OBS1 160
#define OBS2 384
#define TBROW 16
#define SROWS 128
#define S2STR 196
#define S0STR 84
#define S1STR 164
#define CSTR  260

// ---------------- precompute scratch ----------------------------------------
__device__ float g_WkT[256 * 256];
__device__ float g_P[256 * 256];
__device__ float g_G[3 * 256 * 128];
__device__ float g_V2[256 * 128];
__device__ float g_H[768 * 64];
__device__ float g_c[64];

// ---------------- precompute kernels (unchanged from R1) --------------------
__global__ void pre0_transpose(const float* __restrict__ Wk) {
    int t = blockIdx.x, d = threadIdx.x;
    g_WkT[t * 256 + d] = Wk[d * 256 + t];
}
__global__ void pre1(const float* __restrict__ Wq, const float* __restrict__ Wcv,
                     const float* __restrict__ W_out) {
    __shared__ float row[256];
    int bid = blockIdx.x, tid = threadIdx.x;
    if (bid < 256) {
        row[tid] = Wq[bid * 256 + tid];
        __syncthreads();
        float acc = 0.f;
#pragma unroll 8
        for (int t = 0; t < 256; t++) acc = fmaf(row[t], g_WkT[t * 256 + tid], acc);
        g_P[bid * 256 + tid] = acc;
    } else {
        int idx = bid - 256, h = idx >> 8, dd = idx & 255;
        row[tid] = Wcv[dd * 256 + tid];
        __syncthreads();
        if (tid < 128) {
            float acc = 0.f;
#pragma unroll 8
            for (int e = 0; e < 256; e++)
                acc = fmaf(row[e], W_out[(h * 256 + e) * 128 + tid], acc);
            g_G[(h * 256 + dd) * 128 + tid] = acc;
        }
    }
}
__global__ void pre2(const float* __restrict__ Wv, const float* __restrict__ W_j1,
                     const float* __restrict__ b_out, const float* __restrict__ b_j1) {
    __shared__ float row[256];
    int bid = blockIdx.x, tid = threadIdx.x;
    if (bid < 256) {
        row[tid]       = Wv[bid * 256 + tid];
        row[tid + 128] = Wv[bid * 256 + tid + 128];
        __syncthreads();
        float acc = 0.f;
#pragma unroll 8
        for (int e = 0; e < 256; e++)
            acc = fmaf(row[e], g_G[(512 + e) * 128 + tid], acc);
        g_V2[bid * 128 + tid] = acc;
    } else if (bid < 768) {
        int d = bid - 256;
        row[tid] = g_G[d * 128 + tid];
        __syncthreads();
        if (tid < 64) {
            float acc = 0.f;
#pragma unroll 8
            for (int m = 0; m < 128; m++) acc = fmaf(row[m], W_j1[m * 64 + tid], acc);
            g_H[d * 64 + tid] = acc;
        }
    } else {
        if (tid < 64) {
            float acc = b_j1[tid];
#pragma unroll 8
            for (int m = 0; m < 128; m++) acc = fmaf(b_out[m], W_j1[m * 64 + tid], acc);
            g_c[tid] = acc;
        }
    }
}
__global__ void pre3(const float* __restrict__ W_j1) {
    __shared__ float row[128];
    int d2 = blockIdx.x, tid = threadIdx.x;
    row[tid] = g_V2[d2 * 128 + tid];
    __syncthreads();
    if (tid < 64) {
        float acc = 0.f;
#pragma unroll 8
        for (int m = 0; m < 128; m++) acc = fmaf(row[m], W_j1[m * 64 + tid], acc);
        g_H[(512 + d2) * 64 + tid] = acc;
    }
}

// ---------------- tf32 mma helpers ------------------------------------------
__device__ __forceinline__ uint32_t f2tf(float x) {
    uint32_t r; asm("cvt.rna.tf32.f32 %0, %1;" : "=r"(r) : "f"(x)); return r;
}
__device__ __forceinline__ void mma8(float c[4], const uint32_t a[4], const uint32_t b[2]) {
    asm volatile("mma.sync.aligned.m16n8k8.row.col.f32.tf32.tf32.f32 "
        "{%0,%1,%2,%3},{%4,%5,%6,%7},{%8,%9},{%0,%1,%2,%3};"
        : "+f"(c[0]), "+f"(c[1]), "+f"(c[2]), "+f"(c[3])
        : "r"(a[0]), "r"(a[1]), "r"(a[2]), "r"(a[3]), "r"(b[0]), "r"(b[1]));
}
// M=16 GEMM: A in smem (16 x K, stride sA), B in gmem (K x ldb row-major),
// warp computes cols [n0, n0 + NT*8)
template<int KT, int NT>
__device__ __forceinline__ void gemm16(const float* As, int sA,
                                       const float* __restrict__ Bg, int ldb, int n0,
                                       float acc[NT][4], int g, int t) {
#pragma unroll 4
    for (int k = 0; k < KT; k++) {
        int kb = k * 8;
        uint32_t a[4];
        a[0] = f2tf(As[g * sA + kb + t]);
        a[1] = f2tf(As[(g + 8) * sA + kb + t]);
        a[2] = f2tf(As[g * sA + kb + t + 4]);
        a[3] = f2tf(As[(g + 8) * sA + kb + t + 4]);
#pragma unroll
        for (int n = 0; n < NT; n++) {
            uint32_t b[2];
            b[0] = f2tf(Bg[(size_t)(kb + t) * ldb + n0 + n * 8 + g]);
            b[1] = f2tf(Bg[(size_t)(kb + t + 4) * ldb + n0 + n * 8 + g]);
            mma8(acc[n], a, b);
        }
    }
}

// ---------------- main fused kernel ------------------------------------------
// smem f32 offsets
#define OFF_UNI 0          // 33280 (s2 chunk @stride196 / S @stride260)
#define OFF_S0  33280      // 16*84
#define OFF_S1  34624      // 16*164
#define OFF_OWN 37248      // 16*260
#define OFF_ENV 41408
#define OFF_U   45568
#define OFF_SA  49728
#define OFF_H   53888      // 16*64
#define OFF_MS  54912      // 128
#define OFF_SC  55040
#define OFF_AL  55168
#define SMEM_F32 55296
#define SMEM_BYTES (SMEM_F32 * 4)

extern __shared__ float sm[];

__global__ void __launch_bounds__(256, 1)
critic_main(const float* __restrict__ state0, const float* __restrict__ state1,
            const float* __restrict__ state2,
            const float* __restrict__ W_own, const float* __restrict__ b_own,
            const float* __restrict__ W_env, const float* __restrict__ b_env,
            const float* __restrict__ W_sur, const float* __restrict__ b_sur,
            const float* __restrict__ W_j2,  const float* __restrict__ b_j2,
            float* __restrict__ out) {
    float* uni = sm + OFF_UNI;
    float* s0  = sm + OFF_S0;
    float* s1  = sm + OFF_S1;
    float* own = sm + OFF_OWN;
    float* env = sm + OFF_ENV;
    float* u   = sm + OFF_U;
    float* sa  = sm + OFF_SA;
    float* h   = sm + OFF_H;
    float* msum = sm + OFF_MS;
    float* sc  = sm + OFF_SC;
    float* al  = sm + OFF_AL;

    const int tid = threadIdx.x;
    const int w = tid >> 5, lane = tid & 31;
    const int g = lane >> 2, t = lane & 3;
    const int bi = blockIdx.x * TBROW;
    const int n0 = w * 32;                 // 32-col slice for 256-wide GEMMs

    // ---- load s0, s1, s2-chunk0 ----
    for (int i = tid; i < TBROW * OBS0; i += 256)
        s0[(i / OBS0) * S0STR + (i % OBS0)] = state0[(size_t)bi * OBS0 + i];
    for (int i = tid; i < TBROW * OBS1; i += 256)
        s1[(i / OBS1) * S1STR + (i % OBS1)] = state1[(size_t)bi * OBS1 + i];
    for (int i = tid; i < SROWS * 48; i += 256) {
        int rk = i / 48, c4 = i % 48;
        float4 v = *(const float4*)(state2 + ((size_t)bi * 8 + rk) * OBS2 + c4 * 4);
        *(float4*)(uni + rk * S2STR + c4 * 4) = v;
    }
    __syncthreads();

    float accS[8][4][4];
#pragma unroll
    for (int m = 0; m < 8; m++)
#pragma unroll
        for (int n = 0; n < 4; n++)
#pragma unroll
            for (int j = 0; j < 4; j++) accS[m][n][j] = 0.f;

    // ---- chunk0: msum partial + S accum ; plus own/env GEMMs ----
    {
        // own_e
        float acc[4][4] = {};
        gemm16<10, 4>(s0, S0STR, W_own, 256, n0, acc, g, t);
#pragma unroll
        for (int n = 0; n < 4; n++) {
            int col = n0 + n * 8 + 2 * t;
            own[g * CSTR + col]           = fmaxf(acc[n][0] + b_own[col], 0.f);
            own[g * CSTR + col + 1]       = fmaxf(acc[n][1] + b_own[col + 1], 0.f);
            own[(g + 8) * CSTR + col]     = fmaxf(acc[n][2] + b_own[col], 0.f);
            own[(g + 8) * CSTR + col + 1] = fmaxf(acc[n][3] + b_own[col + 1], 0.f);
        }
        // env_e
        float acc2[4][4] = {};
        gemm16<20, 4>(s1, S1STR, W_env, 256, n0, acc2, g, t);
#pragma unroll
        for (int n = 0; n < 4; n++) {
            int col = n0 + n * 8 + 2 * t;
            env[g * CSTR + col]           = fmaxf(acc2[n][0] + b_env[col], 0.f);
            env[g * CSTR + col + 1]       = fmaxf(acc2[n][1] + b_env[col + 1], 0.f);
            env[(g + 8) * CSTR + col]     = fmaxf(acc2[n][2] + b_env[col], 0.f);
            env[(g + 8) * CSTR + col + 1] = fmaxf(acc2[n][3] + b_env[col + 1], 0.f);
        }
        // mask sums (chunk 0)
        for (int i = 0; i < 16; i++) {
            int rk = w * 16 + i;
            float s = 0.f;
#pragma unroll
            for (int j = 0; j < 6; j++) s += uni[rk * S2STR + lane + 32 * j];
#pragma unroll
            for (int off = 16; off > 0; off >>= 1) s += __shfl_xor_sync(0xffffffffu, s, off);
            if (lane == 0) msum[rk] = s;
        }
        // S accum (K rows 0..191)
#pragma unroll 2
        for (int k = 0; k < 24; k++) {
            int kb = k * 8;
            uint32_t b[4][2];
#pragma unroll
            for (int n = 0; n < 4; n++) {
                b[n][0] = f2tf(W_sur[(size_t)(kb + t) * 256 + n0 + n * 8 + g]);
                b[n][1] = f2tf(W_sur[(size_t)(kb + t + 4) * 256 + n0 + n * 8 + g]);
            }
#pragma unroll
            for (int m = 0; m < 8; m++) {
                uint32_t a[4];
                a[0] = f2tf(uni[(m * 16 + g) * S2STR + kb + t]);
                a[1] = f2tf(uni[(m * 16 + g + 8) * S2STR + kb + t]);
                a[2] = f2tf(uni[(m * 16 + g) * S2STR + kb + t + 4]);
                a[3] = f2tf(uni[(m * 16 + g + 8) * S2STR + kb + t + 4]);
#pragma unroll
                for (int n = 0; n < 4; n++) mma8(accS[m][n], a, b[n]);
            }
        }
    }
    __syncthreads();

    // ---- load s2-chunk1 ----
    for (int i = tid; i < SROWS * 48; i += 256) {
        int rk = i / 48, c4 = i % 48;
        float4 v = *(const float4*)(state2 + ((size_t)bi * 8 + rk) * OBS2 + 192 + c4 * 4);
        *(float4*)(uni + rk * S2STR + c4 * 4) = v;
    }
    __syncthreads();

    // ---- chunk1: u GEMM + msum + S accum ----
    {
        float acc[4][4] = {};
        gemm16<32, 4>(own, CSTR, g_P, 256, n0, acc, g, t);
#pragma unroll
        for (int n = 0; n < 4; n++) {
            int col = n0 + n * 8 + 2 * t;
            u[g * CSTR + col]           = acc[n][0];
            u[g * CSTR + col + 1]       = acc[n][1];
            u[(g + 8) * CSTR + col]     = acc[n][2];
            u[(g + 8) * CSTR + col + 1] = acc[n][3];
        }
        for (int i = 0; i < 16; i++) {
            int rk = w * 16 + i;
            float s = 0.f;
#pragma unroll
            for (int j = 0; j < 6; j++) s += uni[rk * S2STR + lane + 32 * j];
#pragma unroll
            for (int off = 16; off > 0; off >>= 1) s += __shfl_xor_sync(0xffffffffu, s, off);
            if (lane == 0) msum[rk] += s;
        }
#pragma unroll 2
        for (int k = 0; k < 24; k++) {
            int kb = k * 8, kg = 192 + kb;
            uint32_t b[4][2];
#pragma unroll
            for (int n = 0; n < 4; n++) {
                b[n][0] = f2tf(W_sur[(size_t)(kg + t) * 256 + n0 + n * 8 + g]);
                b[n][1] = f2tf(W_sur[(size_t)(kg + t + 4) * 256 + n0 + n * 8 + g]);
            }
#pragma unroll
            for (int m = 0; m < 8; m++) {
                uint32_t a[4];
                a[0] = f2tf(uni[(m * 16 + g) * S2STR + kb + t]);
                a[1] = f2tf(uni[(m * 16 + g + 8) * S2STR + kb + t]);
                a[2] = f2tf(uni[(m * 16 + g) * S2STR + kb + t + 4]);
                a[3] = f2tf(uni[(m * 16 + g + 8) * S2STR + kb + t + 4]);
#pragma unroll
                for (int n = 0; n < 4; n++) mma8(accS[m][n], a, b[n]);
            }
        }
    }
    __syncthreads();

    // ---- store S = relu(acc + b_sur) into uni (stride CSTR) ----
#pragma unroll
    for (int m = 0; m < 8; m++)
#pragma unroll
        for (int n = 0; n < 4; n++) {
            int col = n0 + n * 8 + 2 * t;
            int r0 = m * 16 + g, r1 = r0 + 8;
            float bb0 = b_sur[col], bb1 = b_sur[col + 1];
            uni[r0 * CSTR + col]     = fmaxf(accS[m][n][0] + bb0, 0.f);
            uni[r0 * CSTR + col + 1] = fmaxf(accS[m][n][1] + bb1, 0.f);
            uni[r1 * CSTR + col]     = fmaxf(accS[m][n][2] + bb0, 0.f);
            uni[r1 * CSTR + col + 1] = fmaxf(accS[m][n][3] + bb1, 0.f);
        }
    __syncthreads();

    // ---- score ----
    for (int i = 0; i < 16; i++) {
        int rk = w * 16 + i, r = rk >> 3;
        float dot = 0.f;
#pragma unroll
        for (int j = 0; j < 8; j++)
            dot = fmaf(uni[rk * CSTR + lane + 32 * j], u[r * CSTR + lane + 32 * j], dot);
#pragma unroll
        for (int off = 16; off > 0; off >>= 1) dot += __shfl_xor_sync(0xffffffffu, dot, off);
        if (lane == 0) sc[rk] = (msum[rk] != 0.f) ? dot * 0.0625f : -INFINITY;
    }
    __syncthreads();

    // ---- softmax over K=8 per row ----
    if (tid < 128) {
        float s = sc[tid];
        float m = s;
#pragma unroll
        for (int off = 1; off < 8; off <<= 1)
            m = fmaxf(m, __shfl_xor_sync(0xffffffffu, m, off));
        float e = (s == -INFINITY) ? 0.f : expf(s - m);
        float ssum = e;
#pragma unroll
        for (int off = 1; off < 8; off <<= 1)
            ssum += __shfl_xor_sync(0xffffffffu, ssum, off);
        al[tid] = e / ssum;
    }
    __syncthreads();

    // ---- s_att ----
    {
        int d = tid;
#pragma unroll
        for (int r = 0; r < 16; r++) {
            float acc = 0.f;
#pragma unroll
            for (int kk = 0; kk < 8; kk++)
                acc = fmaf(al[r * 8 + kk], uni[(r * 8 + kk) * CSTR + d], acc);
            sa[r * CSTR + d] = acc;
        }
    }
    __syncthreads();

    // ---- tail: hidden = relu([own|env|sa] @ H + c) ----
    {
        int nt = w * 8;
        float acc3[1][4] = {};
        gemm16<32, 1>(own, CSTR, g_H,            64, nt, acc3, g, t);
        gemm16<32, 1>(env, CSTR, g_H + 256 * 64, 64, nt, acc3, g, t);
        gemm16<32, 1>(sa,  CSTR, g_H + 512 * 64, 64, nt, acc3, g, t);
        int col = nt + 2 * t;
        h[g * 64 + col]           = fmaxf(acc3[0][0] + g_c[col], 0.f);
        h[g * 64 + col + 1]       = fmaxf(acc3[0][1] + g_c[col + 1], 0.f);
        h[(g + 8) * 64 + col]     = fmaxf(acc3[0][2] + g_c[col], 0.f);
        h[(g + 8) * 64 + col + 1] = fmaxf(acc3[0][3] + g_c[col + 1], 0.f);
    }
    __syncthreads();

    // ---- output ----
    if (tid < 128) {
        int r = tid >> 3, gg = tid & 7;
        float ssum = 0.f;
#pragma unroll
        for (int i = 0; i < 8; i++)
            ssum = fmaf(h[r * 64 + gg + 8 * i], W_j2[gg + 8 * i], ssum);
#pragma unroll
        for (int off = 1; off < 8; off <<= 1)
            ssum += __shfl_xor_sync(0xffffffffu, ssum, off);
        if (gg == 0) out[bi + r] = ssum + b_j2[0];
    }
}

// ---------------- launch ------------------------------------------------------
extern "C" void kernel_launch(void* const* d_in, const int* in_sizes, int n_in,
                              void* d_out, int out_size) {
    const float* state0 = (const float*)d_in[0];
    const float* state1 = (const float*)d_in[1];
    const float* state2 = (const float*)d_in[2];
    const float* W_own  = (const float*)d_in[3];
    const float* b_own  = (const float*)d_in[4];
    const float* W_env  = (const float*)d_in[5];
    const float* b_env  = (const float*)d_in[6];
    const float* W_sur  = (const float*)d_in[7];
    const float* b_sur  = (const float*)d_in[8];
    const float* Wq     = (const float*)d_in[9];
    const float* Wk     = (const float*)d_in[10];
    const float* Wv     = (const float*)d_in[11];
    const float* Wcv    = (const float*)d_in[14];
    const float* W_out  = (const float*)d_in[15];
    const float* b_out  = (const float*)d_in[16];
    const float* W_j1   = (const float*)d_in[17];
    const float* b_j1   = (const float*)d_in[18];
    const float* W_j2   = (const float*)d_in[19];
    const float* b_j2   = (const float*)d_in[20];
    float* out = (float*)d_out;

    int B = in_sizes[0] / OBS0;

    cudaFuncSetAttribute(critic_main, cudaFuncAttributeMaxDynamicSharedMemorySize,
                         SMEM_BYTES);

    pre0_transpose<<<256, 256>>>(Wk);
    pre1<<<1024, 256>>>(Wq, Wcv, W_out);
    pre2<<<769, 128>>>(Wv, W_j1, b_out, b_j1);
    pre3<<<256, 128>>>(W_j1);
    critic_main<<<B / TBROW, 256, SMEM_BYTES>>>(state0, state1, state2,
                                                W_own, b_own, W_env, b_env,
                                                W_sur, b_sur, W_j2, b_j2, out);
}